// round 2
// baseline (speedup 1.0000x reference)
#include <cuda_runtime.h>

#define BN 8
#define IC 512
#define OC 512
#define HH 32
#define WW 32

// fan_in scaling constants
#define RC_DENSE 0.04419417382415922f     // 1/sqrt(512)
#define RC_CONV  0.014731391274719739f    // 1/sqrt(9*512)

// scratch (no allocations allowed)
__device__ float g_style[BN * IC];   // style[b,ic] = RC_DENSE * (w @ dense_w) + b + 1
__device__ float g_scale[BN * OC];   // RC_CONV * d[b,oc]
__device__ float g_ss[IC * OC];      // sum_k conv_w[k,ic,oc]^2

// ---------------------------------------------------------------------------
// style[b,i] = RC_DENSE * sum_j w[b,j] * dense_w[j,i] + dense_b[i] + 1
// ---------------------------------------------------------------------------
__global__ void style_kernel(const float* __restrict__ w,
                             const float* __restrict__ dense_w,
                             const float* __restrict__ dense_b) {
    __shared__ float wrow[IC];
    int b = blockIdx.x;
    for (int j = threadIdx.x; j < IC; j += blockDim.x) wrow[j] = w[b * IC + j];
    __syncthreads();
    for (int i = threadIdx.x; i < IC; i += blockDim.x) {
        float acc = 0.f;
        #pragma unroll 8
        for (int j = 0; j < IC; j++) acc = fmaf(wrow[j], dense_w[j * IC + i], acc);
        g_style[b * IC + i] = RC_DENSE * acc + dense_b[i] + 1.0f;
    }
}

// ---------------------------------------------------------------------------
// ss[ic,oc] = sum_k conv_w[k,ic,oc]^2
// ---------------------------------------------------------------------------
__global__ void ss_kernel(const float* __restrict__ conv_w) {
    int idx = blockIdx.x * blockDim.x + threadIdx.x;  // ic*OC + oc
    if (idx >= IC * OC) return;
    float s = 0.f;
    #pragma unroll
    for (int k = 0; k < 9; k++) {
        float v = conv_w[k * IC * OC + idx];
        s = fmaf(v, v, s);
    }
    g_ss[idx] = s;
}

// ---------------------------------------------------------------------------
// scale[b,oc] = RC_CONV * rsqrt(RC_CONV^2 * sum_ic style[b,ic]^2 * ss[ic,oc] + 1e-8)
// ---------------------------------------------------------------------------
__global__ void demod_kernel() {
    __shared__ float s2[IC];
    int b = blockIdx.x;
    for (int i = threadIdx.x; i < IC; i += blockDim.x) {
        float s = g_style[b * IC + i];
        s2[i] = s * s;
    }
    __syncthreads();
    for (int oc = threadIdx.x; oc < OC; oc += blockDim.x) {
        float acc = 0.f;
        #pragma unroll 8
        for (int i = 0; i < IC; i++) acc = fmaf(s2[i], g_ss[i * OC + oc], acc);
        g_scale[b * OC + oc] = RC_CONV * rsqrtf(RC_CONV * RC_CONV * acc + 1e-8f);
    }
}

// ---------------------------------------------------------------------------
// Conv: y[b,oc,h,w] = scale[b,oc] * sum_{ic,kh,kw} conv_w[kh,kw,ic,oc]
//                                   * style[b,ic] * x[b,ic,h+kh-1,w+kw-1]
// Block: 64 oc x (4 rows x 32 cols) for one batch. 256 threads.
//   lane (tx&31) = column, ocg (tx>>5) = group of 8 oc.
// ---------------------------------------------------------------------------
#define ICC   8
#define TOC   64
#define TROWS 4

__global__ __launch_bounds__(256, 2)
void conv_kernel(const float* __restrict__ x,
                 const float* __restrict__ conv_w,
                 float* __restrict__ y) {
    int b   = blockIdx.z;
    int oc0 = blockIdx.y * TOC;
    int y0  = blockIdx.x * TROWS;

    __shared__ float s_style[IC];           // 2 KB
    __shared__ float xs[ICC][6][34];        // 6.4 KB  (rows y0-1..y0+4, cols -1..32)
    __shared__ float ws[9][ICC][TOC];       // 18 KB

    int tx   = threadIdx.x;
    int lane = tx & 31;   // output column
    int ocg  = tx >> 5;   // oc group (8 oc each)

    for (int i = tx; i < IC; i += 256) s_style[i] = g_style[b * IC + i];

    float acc[TROWS][8];
    #pragma unroll
    for (int r = 0; r < TROWS; r++)
        #pragma unroll
        for (int o = 0; o < 8; o++) acc[r][o] = 0.f;

    __syncthreads();

    for (int ic0 = 0; ic0 < IC; ic0 += ICC) {
        // ---- load weight slab: ws[k][ic][oc] ----
        #pragma unroll
        for (int t = tx; t < 9 * ICC * TOC; t += 256) {
            int k   = t / (ICC * TOC);
            int rem = t % (ICC * TOC);
            int ic  = rem / TOC;
            int oc  = rem % TOC;
            ws[k][ic][oc] = conv_w[(k * IC + ic0 + ic) * OC + oc0 + oc];
        }
        // ---- load modulated x halo tile ----
        #pragma unroll
        for (int t = tx; t < ICC * 6 * 34; t += 256) {
            int ic  = t / (6 * 34);
            int rem = t % (6 * 34);
            int row = rem / 34;
            int col = rem % 34;
            int gr = y0 - 1 + row;
            int gc = col - 1;
            float v = 0.f;
            if (gr >= 0 && gr < HH && gc >= 0 && gc < WW)
                v = x[((b * IC + ic0 + ic) * HH + gr) * WW + gc] * s_style[ic0 + ic];
            xs[ic][row][col] = v;
        }
        __syncthreads();

        #pragma unroll
        for (int ic = 0; ic < ICC; ic++) {
            // x neighborhood for this thread's column: rows 0..5, cols lane..lane+2
            float xv[6][3];
            #pragma unroll
            for (int rr = 0; rr < 6; rr++)
                #pragma unroll
                for (int c = 0; c < 3; c++)
                    xv[rr][c] = xs[ic][rr][lane + c];

            #pragma unroll
            for (int kh = 0; kh < 3; kh++)
                #pragma unroll
                for (int kw = 0; kw < 3; kw++) {
                    float wv[8];
                    #pragma unroll
                    for (int o = 0; o < 8; o++)
                        wv[o] = ws[kh * 3 + kw][ic][ocg * 8 + o];
                    #pragma unroll
                    for (int r = 0; r < TROWS; r++) {
                        float xvv = xv[r + kh][kw];
                        #pragma unroll
                        for (int o = 0; o < 8; o++)
                            acc[r][o] = fmaf(xvv, wv[o], acc[r][o]);
                    }
                }
        }
        __syncthreads();
    }

    // ---- epilogue: demodulate and store ----
    #pragma unroll
    for (int o = 0; o < 8; o++) {
        int oc = oc0 + ocg * 8 + o;
        float sc = g_scale[b * OC + oc];
        #pragma unroll
        for (int r = 0; r < TROWS; r++)
            y[((b * OC + oc) * HH + y0 + r) * WW + lane] = acc[r][o] * sc;
    }
}

// ---------------------------------------------------------------------------
extern "C" void kernel_launch(void* const* d_in, const int* in_sizes, int n_in,
                              void* d_out, int out_size) {
    const float* x       = (const float*)d_in[0];
    const float* w       = (const float*)d_in[1];
    const float* conv_w  = (const float*)d_in[2];
    const float* dense_w = (const float*)d_in[3];
    const float* dense_b = (const float*)d_in[4];
    float* y = (float*)d_out;

    style_kernel<<<BN, 256>>>(w, dense_w, dense_b);
    ss_kernel<<<(IC * OC) / 256, 256>>>(conv_w);
    demod_kernel<<<BN, 512>>>();

    dim3 grid(HH / TROWS, OC / TOC, BN);   // 8 x 8 x 8
    conv_kernel<<<grid, 256>>>(x, conv_w, y);
}

// round 5
// speedup vs baseline: 1.8540x; 1.8540x over previous
#include <cuda_runtime.h>
#include <cuda_bf16.h>
#include <cstdint>

#define BN 8
#define IC 512
#define OC 512
#define HH 32
#define WW 32

#define RC_DENSE 0.04419417382415922f     // 1/sqrt(512)
#define RC_CONV  0.014731391274719739f    // 1/sqrt(9*512)

// ---------------- device scratch (no runtime allocation) ----------------
__device__ float g_style[BN * IC];
__device__ float g_scale[BN * OC];
__device__ float g_ss[IC * OC];
// weights transposed to [tap][oc][ic], split hi/lo bf16
__device__ __align__(128) __nv_bfloat16 g_wq_hi[9 * OC * IC];
__device__ __align__(128) __nv_bfloat16 g_wq_lo[9 * OC * IC];
// modulated input in NHWC: [b][h][w][ic], split hi/lo bf16
__device__ __align__(128) __nv_bfloat16 g_xm_hi[BN * HH * WW * IC];
__device__ __align__(128) __nv_bfloat16 g_xm_lo[BN * HH * WW * IC];

// ---------------- prologue kernels ----------------
__global__ void style_kernel(const float* __restrict__ w,
                             const float* __restrict__ dense_w,
                             const float* __restrict__ dense_b) {
    __shared__ float wrow[IC];
    int b = blockIdx.x;
    for (int j = threadIdx.x; j < IC; j += blockDim.x) wrow[j] = w[b * IC + j];
    __syncthreads();
    for (int i = threadIdx.x; i < IC; i += blockDim.x) {
        float acc = 0.f;
        #pragma unroll 8
        for (int j = 0; j < IC; j++) acc = fmaf(wrow[j], dense_w[j * IC + i], acc);
        g_style[b * IC + i] = RC_DENSE * acc + dense_b[i] + 1.0f;
    }
}

__global__ void ss_kernel(const float* __restrict__ conv_w) {
    int idx = blockIdx.x * blockDim.x + threadIdx.x;
    if (idx >= IC * OC) return;
    float s = 0.f;
    #pragma unroll
    for (int k = 0; k < 9; k++) {
        float v = conv_w[k * IC * OC + idx];
        s = fmaf(v, v, s);
    }
    g_ss[idx] = s;
}

__global__ void demod_kernel() {
    __shared__ float s2[IC];
    int b = blockIdx.x;
    for (int i = threadIdx.x; i < IC; i += blockDim.x) {
        float s = g_style[b * IC + i];
        s2[i] = s * s;
    }
    __syncthreads();
    for (int oc = threadIdx.x; oc < OC; oc += blockDim.x) {
        float acc = 0.f;
        #pragma unroll 8
        for (int i = 0; i < IC; i++) acc = fmaf(s2[i], g_ss[i * OC + oc], acc);
        g_scale[b * OC + oc] = RC_CONV * rsqrtf(RC_CONV * RC_CONV * acc + 1e-8f);
    }
}

// conv_w[k][ic][oc] -> wq[k][oc][ic] (hi/lo bf16)
__global__ void wtrans_kernel(const float* __restrict__ conv_w) {
    __shared__ float tile[32][33];
    int ic0 = blockIdx.x * 32, oc0 = blockIdx.y * 32, k = blockIdx.z;
    int t = threadIdx.x, col = t & 31, row0 = t >> 5;
    #pragma unroll
    for (int rr = 0; rr < 4; rr++) {
        int i = rr * 8 + row0;  // ic
        tile[i][col] = conv_w[((size_t)(k * IC + ic0 + i)) * OC + oc0 + col];
    }
    __syncthreads();
    int r = t >> 3, pp = t & 7;  // r = oc row within tile
    size_t base = ((size_t)(k * OC + oc0 + r)) * IC + ic0;
    #pragma unroll
    for (int it = 0; it < 2; it++) {
        int ci = 2 * (it * 8 + pp);
        float v0 = tile[ci][r], v1 = tile[ci + 1][r];
        __nv_bfloat16 h0 = __float2bfloat16(v0), h1 = __float2bfloat16(v1);
        __nv_bfloat16 l0 = __float2bfloat16(v0 - __bfloat162float(h0));
        __nv_bfloat16 l1 = __float2bfloat16(v1 - __bfloat162float(h1));
        *(__nv_bfloat162*)(g_wq_hi + base + ci) = __halves2bfloat162(h0, h1);
        *(__nv_bfloat162*)(g_wq_lo + base + ci) = __halves2bfloat162(l0, l1);
    }
}

// x[b][ic][h][w] * style[b][ic] -> xm[b][h][w][ic] (hi/lo bf16)
__global__ void xtrans_kernel(const float* __restrict__ x) {
    __shared__ float tile[32][33];
    int ic0 = blockIdx.x * 32, h = blockIdx.y, b = blockIdx.z;
    int t = threadIdx.x, col = t & 31, row0 = t >> 5;
    #pragma unroll
    for (int rr = 0; rr < 4; rr++) {
        int i = rr * 8 + row0;  // ic
        tile[i][col] = x[(((size_t)b * IC + ic0 + i) * HH + h) * WW + col] * g_style[b * IC + ic0 + i];
    }
    __syncthreads();
    int w = t >> 3, pp = t & 7;
    size_t base = (((size_t)b * HH + h) * WW + w) * IC + ic0;
    #pragma unroll
    for (int it = 0; it < 2; it++) {
        int ci = 2 * (it * 8 + pp);
        float v0 = tile[ci][w], v1 = tile[ci + 1][w];
        __nv_bfloat16 h0 = __float2bfloat16(v0), h1 = __float2bfloat16(v1);
        __nv_bfloat16 l0 = __float2bfloat16(v0 - __bfloat162float(h0));
        __nv_bfloat16 l1 = __float2bfloat16(v1 - __bfloat162float(h1));
        *(__nv_bfloat162*)(g_xm_hi + base + ci) = __halves2bfloat162(h0, h1);
        *(__nv_bfloat162*)(g_xm_lo + base + ci) = __halves2bfloat162(l0, l1);
    }
}

// ---------------- main mma.sync conv kernel ----------------
// CTA tile: M=128 (4 h-rows x 32 w) x N=128 oc. 8 warps (4 along M x 2 along N),
// warp tile 32x64. K streamed: 9 taps x (512/32) ic-chunks. Single smem stage,
// 2 CTAs/SM hide latency. Split-bf16: acc += Ah*Bh + Ah*Bl + Al*Bh.
#define KC 32
#define PAD_K 56           // padded row stride in halves (112 B: 16B-aligned, conflict-free)

__device__ __forceinline__ void mma_bf16(float& c0, float& c1, float& c2, float& c3,
                                         uint32_t a0, uint32_t a1, uint32_t a2, uint32_t a3,
                                         uint32_t b0, uint32_t b1) {
    asm volatile(
        "mma.sync.aligned.m16n8k16.row.col.f32.bf16.bf16.f32 "
        "{%0,%1,%2,%3}, {%4,%5,%6,%7}, {%8,%9}, {%0,%1,%2,%3};"
        : "+f"(c0), "+f"(c1), "+f"(c2), "+f"(c3)
        : "r"(a0), "r"(a1), "r"(a2), "r"(a3), "r"(b0), "r"(b1));
}

__global__ __launch_bounds__(256, 2)
void conv_mma_kernel(float* __restrict__ y) {
    __shared__ unsigned short As_hi[128 * PAD_K];
    __shared__ unsigned short As_lo[128 * PAD_K];
    __shared__ unsigned short Bs_hi[128 * PAD_K];
    __shared__ unsigned short Bs_lo[128 * PAD_K];

    const int tid = threadIdx.x;
    const int wid = tid >> 5, lane = tid & 31;
    const int gr = lane >> 2, tig = lane & 3;
    const int wm = wid & 3;        // warp m index (h-row)
    const int wn = wid >> 2;       // warp n index (0/1)

    const int h0 = blockIdx.x * 4;
    const int oc0 = blockIdx.y * 128;
    const int b = blockIdx.z;

    // per-thread global-load coords
    const int mrow = tid >> 1;              // 0..127
    const int rr = mrow >> 5;               // h-row within tile
    const int wcol = mrow & 31;             // w coordinate
    const int half = tid & 1;               // which 32B half of the 64B row

    float acc[2][8][4];
    #pragma unroll
    for (int mt = 0; mt < 2; mt++)
        #pragma unroll
        for (int nt = 0; nt < 8; nt++)
            #pragma unroll
            for (int q = 0; q < 4; q++) acc[mt][nt][q] = 0.f;

    for (int kk = 0; kk < 9; kk++) {
        const int dh = kk / 3 - 1, dw = kk % 3 - 1;
        const int hh = h0 + rr + dh, ws = wcol + dw;
        const bool valid = ((unsigned)hh < HH) && ((unsigned)ws < WW);
        const size_t arow = valid ? ((((size_t)b * HH + hh) * WW + ws) * IC) : 0;
        const size_t brow = ((size_t)kk * OC + oc0 + mrow) * IC;

        for (int ic0 = 0; ic0 < IC; ic0 += KC) {
            __syncthreads();
            // ---- load A tile (128 x 32 halves, hi+lo), 32B per thread per array ----
            {
                const uint4* sh = (const uint4*)(g_xm_hi + arow + ic0 + half * 16);
                const uint4* sl = (const uint4*)(g_xm_lo + arow + ic0 + half * 16);
                uint4 z = make_uint4(0, 0, 0, 0);
                uint4 h0v = valid ? sh[0] : z, h1v = valid ? sh[1] : z;
                uint4 l0v = valid ? sl[0] : z, l1v = valid ? sl[1] : z;
                uint4* d0 = (uint4*)(As_hi + mrow * PAD_K + half * 16);
                uint4* d1 = (uint4*)(As_lo + mrow * PAD_K + half * 16);
                d0[0] = h0v; d0[1] = h1v;
                d1[0] = l0v; d1[1] = l1v;
            }
            // ---- load B tile (128 oc-rows x 32 halves, hi+lo) ----
            {
                const uint4* sh = (const uint4*)(g_wq_hi + brow + ic0 + half * 16);
                const uint4* sl = (const uint4*)(g_wq_lo + brow + ic0 + half * 16);
                uint4 h0v = sh[0], h1v = sh[1];
                uint4 l0v = sl[0], l1v = sl[1];
                uint4* d0 = (uint4*)(Bs_hi + mrow * PAD_K + half * 16);
                uint4* d1 = (uint4*)(Bs_lo + mrow * PAD_K + half * 16);
                d0[0] = h0v; d0[1] = h1v;
                d1[0] = l0v; d1[1] = l1v;
            }
            __syncthreads();

            // ---- compute: 2 k-slices of 16 ----
            #pragma unroll
            for (int ks = 0; ks < 2; ks++) {
                const int kb = ks * 16 + tig * 2;
                uint32_t ah[2][4], al[2][4];
                #pragma unroll
                for (int mt = 0; mt < 2; mt++) {
                    int r0 = (wm * 32 + mt * 16 + gr) * PAD_K + kb;
                    int r1 = r0 + 8 * PAD_K;
                    ah[mt][0] = *(const uint32_t*)(As_hi + r0);
                    ah[mt][1] = *(const uint32_t*)(As_hi + r1);
                    ah[mt][2] = *(const uint32_t*)(As_hi + r0 + 8);
                    ah[mt][3] = *(const uint32_t*)(As_hi + r1 + 8);
                    al[mt][0] = *(const uint32_t*)(As_lo + r0);
                    al[mt][1] = *(const uint32_t*)(As_lo + r1);
                    al[mt][2] = *(const uint32_t*)(As_lo + r0 + 8);
                    al[mt][3] = *(const uint32_t*)(As_lo + r1 + 8);
                }
                #pragma unroll
                for (int nt = 0; nt < 8; nt++) {
                    int rb = (wn * 64 + nt * 8 + gr) * PAD_K + kb;
                    uint32_t bh0 = *(const uint32_t*)(Bs_hi + rb);
                    uint32_t bh1 = *(const uint32_t*)(Bs_hi + rb + 8);
                    uint32_t bl0 = *(const uint32_t*)(Bs_lo + rb);
                    uint32_t bl1 = *(const uint32_t*)(Bs_lo + rb + 8);
                    #pragma unroll
                    for (int mt = 0; mt < 2; mt++) {
                        float* c = acc[mt][nt];
                        mma_bf16(c[0], c[1], c[2], c[3],
                                 ah[mt][0], ah[mt][1], ah[mt][2], ah[mt][3], bh0, bh1);
                        mma_bf16(c[0], c[1], c[2], c[3],
                                 ah[mt][0], ah[mt][1], ah[mt][2], ah[mt][3], bl0, bl1);
                        mma_bf16(c[0], c[1], c[2], c[3],
                                 al[mt][0], al[mt][1], al[mt][2], al[mt][3], bh0, bh1);
                    }
                }
            }
        }
    }

    // ---- epilogue: demodulate + store ----
    // warp wm owns h-row h0+wm entirely; thread element (mt,nt,q):
    //   w = mt*16 + gr (+8 for q>=2), oc = oc0 + wn*64 + nt*8 + tig*2 + (q&1)
    const int h = h0 + wm;
    float scl[8][2];
    #pragma unroll
    for (int nt = 0; nt < 8; nt++) {
        int oc = oc0 + wn * 64 + nt * 8 + tig * 2;
        scl[nt][0] = g_scale[b * OC + oc];
        scl[nt][1] = g_scale[b * OC + oc + 1];
    }
    #pragma unroll
    for (int mt = 0; mt < 2; mt++) {
        int w0 = mt * 16 + gr;
        #pragma unroll
        for (int nt = 0; nt < 8; nt++) {
            int oc = oc0 + wn * 64 + nt * 8 + tig * 2;
            size_t base0 = (((size_t)b * OC + oc) * HH + h) * WW;
            size_t base1 = base0 + (size_t)HH * WW;
            y[base0 + w0]     = acc[mt][nt][0] * scl[nt][0];
            y[base1 + w0]     = acc[mt][nt][1] * scl[nt][1];
            y[base0 + w0 + 8] = acc[mt][nt][2] * scl[nt][0];
            y[base1 + w0 + 8] = acc[mt][nt][3] * scl[nt][1];
        }
    }
}

// ---------------------------------------------------------------------------
extern "C" void kernel_launch(void* const* d_in, const int* in_sizes, int n_in,
                              void* d_out, int out_size) {
    const float* x       = (const float*)d_in[0];
    const float* w       = (const float*)d_in[1];
    const float* conv_w  = (const float*)d_in[2];
    const float* dense_w = (const float*)d_in[3];
    const float* dense_b = (const float*)d_in[4];
    float* y = (float*)d_out;

    style_kernel<<<BN, 256>>>(w, dense_w, dense_b);
    ss_kernel<<<(IC * OC) / 256, 256>>>(conv_w);
    demod_kernel<<<BN, 512>>>();
    wtrans_kernel<<<dim3(IC / 32, OC / 32, 9), 256>>>(conv_w);
    xtrans_kernel<<<dim3(IC / 32, HH, BN), 256>>>(x);

    conv_mma_kernel<<<dim3(8, 4, BN), 256>>>(y);
}

// round 6
// speedup vs baseline: 2.3282x; 1.2557x over previous
#include <cuda_runtime.h>
#include <cuda_bf16.h>
#include <cstdint>

#define BN 8
#define IC 512
#define OC 512
#define HH 32
#define WW 32

#define RC_DENSE 0.04419417382415922f     // 1/sqrt(512)
#define RC_CONV  0.014731391274719739f    // 1/sqrt(9*512)

// ---------------- device scratch (no runtime allocation) ----------------
__device__ float g_style[BN * IC];
__device__ float g_scale[BN * OC];
__device__ float g_ss[IC * OC];
// weights transposed to [tap][oc][ic], split hi/lo bf16
__device__ __align__(128) __nv_bfloat16 g_wq_hi[9 * OC * IC];
__device__ __align__(128) __nv_bfloat16 g_wq_lo[9 * OC * IC];
// modulated input in NHWC: [b][h][w][ic], split hi/lo bf16
__device__ __align__(128) __nv_bfloat16 g_xm_hi[BN * HH * WW * IC];
__device__ __align__(128) __nv_bfloat16 g_xm_lo[BN * HH * WW * IC];

// ---------------- prologue kernels ----------------
__global__ void style_kernel(const float* __restrict__ w,
                             const float* __restrict__ dense_w,
                             const float* __restrict__ dense_b) {
    __shared__ float wrow[IC];
    int b = blockIdx.x;
    for (int j = threadIdx.x; j < IC; j += blockDim.x) wrow[j] = w[b * IC + j];
    __syncthreads();
    for (int i = threadIdx.x; i < IC; i += blockDim.x) {
        float acc = 0.f;
        #pragma unroll 8
        for (int j = 0; j < IC; j++) acc = fmaf(wrow[j], dense_w[j * IC + i], acc);
        g_style[b * IC + i] = RC_DENSE * acc + dense_b[i] + 1.0f;
    }
}

__global__ void ss_kernel(const float* __restrict__ conv_w) {
    int idx = blockIdx.x * blockDim.x + threadIdx.x;
    if (idx >= IC * OC) return;
    float s = 0.f;
    #pragma unroll
    for (int k = 0; k < 9; k++) {
        float v = conv_w[k * IC * OC + idx];
        s = fmaf(v, v, s);
    }
    g_ss[idx] = s;
}

__global__ void demod_kernel() {
    __shared__ float s2[IC];
    int b = blockIdx.x;
    for (int i = threadIdx.x; i < IC; i += blockDim.x) {
        float s = g_style[b * IC + i];
        s2[i] = s * s;
    }
    __syncthreads();
    for (int oc = threadIdx.x; oc < OC; oc += blockDim.x) {
        float acc = 0.f;
        #pragma unroll 8
        for (int i = 0; i < IC; i++) acc = fmaf(s2[i], g_ss[i * OC + oc], acc);
        g_scale[b * OC + oc] = RC_CONV * rsqrtf(RC_CONV * RC_CONV * acc + 1e-8f);
    }
}

// conv_w[k][ic][oc] -> wq[k][oc][ic] (hi/lo bf16)
__global__ void wtrans_kernel(const float* __restrict__ conv_w) {
    __shared__ float tile[32][33];
    int ic0 = blockIdx.x * 32, oc0 = blockIdx.y * 32, k = blockIdx.z;
    int t = threadIdx.x, col = t & 31, row0 = t >> 5;
    #pragma unroll
    for (int rr = 0; rr < 4; rr++) {
        int i = rr * 8 + row0;  // ic
        tile[i][col] = conv_w[((size_t)(k * IC + ic0 + i)) * OC + oc0 + col];
    }
    __syncthreads();
    int r = t >> 3, pp = t & 7;  // r = oc row within tile
    size_t base = ((size_t)(k * OC + oc0 + r)) * IC + ic0;
    #pragma unroll
    for (int it = 0; it < 2; it++) {
        int ci = 2 * (it * 8 + pp);
        float v0 = tile[ci][r], v1 = tile[ci + 1][r];
        __nv_bfloat16 h0 = __float2bfloat16(v0), h1 = __float2bfloat16(v1);
        __nv_bfloat16 l0 = __float2bfloat16(v0 - __bfloat162float(h0));
        __nv_bfloat16 l1 = __float2bfloat16(v1 - __bfloat162float(h1));
        *(__nv_bfloat162*)(g_wq_hi + base + ci) = __halves2bfloat162(h0, h1);
        *(__nv_bfloat162*)(g_wq_lo + base + ci) = __halves2bfloat162(l0, l1);
    }
}

// x[b][ic][h][w] * style[b][ic] -> xm[b][h][w][ic] (hi/lo bf16)
__global__ void xtrans_kernel(const float* __restrict__ x) {
    __shared__ float tile[32][33];
    int ic0 = blockIdx.x * 32, h = blockIdx.y, b = blockIdx.z;
    int t = threadIdx.x, col = t & 31, row0 = t >> 5;
    #pragma unroll
    for (int rr = 0; rr < 4; rr++) {
        int i = rr * 8 + row0;  // ic
        tile[i][col] = x[(((size_t)b * IC + ic0 + i) * HH + h) * WW + col] * g_style[b * IC + ic0 + i];
    }
    __syncthreads();
    int w = t >> 3, pp = t & 7;
    size_t base = (((size_t)b * HH + h) * WW + w) * IC + ic0;
    #pragma unroll
    for (int it = 0; it < 2; it++) {
        int ci = 2 * (it * 8 + pp);
        float v0 = tile[ci][w], v1 = tile[ci + 1][w];
        __nv_bfloat16 h0 = __float2bfloat16(v0), h1 = __float2bfloat16(v1);
        __nv_bfloat16 l0 = __float2bfloat16(v0 - __bfloat162float(h0));
        __nv_bfloat16 l1 = __float2bfloat16(v1 - __bfloat162float(h1));
        *(__nv_bfloat162*)(g_xm_hi + base + ci) = __halves2bfloat162(h0, h1);
        *(__nv_bfloat162*)(g_xm_lo + base + ci) = __halves2bfloat162(l0, l1);
    }
}

// ---------------- main mma.sync conv kernel ----------------
// CTA tile: M=128 (4 h x 32 w) x N=128 oc. 8 warps (4 M x 2 N), warp 32x64.
// Per ic-chunk (KC=32): A staged ONCE as 6x34 (h,w)-halo w/ zero borders; all
// 9 taps read shifted smem. B(tap) double-buffered via cp.async.
// Fragments via ldmatrix.x4. Split-bf16: acc += Ah*Bh + Ah*Bl + Al*Bh.
#define KC 32
#define PAD_A 40   // halves per (h,w) halo position (80B, conflict-free ldmatrix)
#define PAD_B 40

// smem offsets in halves
#define A_HI_O 0
#define A_LO_O 8160
#define B_ARR  5120
#define B_O(buf) (16320 + (buf) * 10240)
#define SM_HALVES 36800      // 73600 bytes

__device__ __forceinline__ void mma_bf16(float* c,
                                         const uint32_t* a, uint32_t b0, uint32_t b1) {
    asm volatile(
        "mma.sync.aligned.m16n8k16.row.col.f32.bf16.bf16.f32 "
        "{%0,%1,%2,%3}, {%4,%5,%6,%7}, {%8,%9}, {%0,%1,%2,%3};"
        : "+f"(c[0]), "+f"(c[1]), "+f"(c[2]), "+f"(c[3])
        : "r"(a[0]), "r"(a[1]), "r"(a[2]), "r"(a[3]), "r"(b0), "r"(b1));
}

__device__ __forceinline__ void ldsm4(uint32_t* r, uint32_t a) {
    asm volatile("ldmatrix.sync.aligned.m8n8.x4.shared.b16 {%0,%1,%2,%3}, [%4];"
                 : "=r"(r[0]), "=r"(r[1]), "=r"(r[2]), "=r"(r[3]) : "r"(a));
}

__device__ __forceinline__ void cp16(uint32_t dst, const void* src, bool v) {
    asm volatile("cp.async.ca.shared.global [%0], [%1], 16, %2;"
                 :: "r"(dst), "l"(src), "r"(v ? 16 : 0) : "memory");
}
#define CP_COMMIT() asm volatile("cp.async.commit_group;" ::: "memory")
#define CP_WAIT0()  asm volatile("cp.async.wait_group 0;" ::: "memory")

__device__ __forceinline__ uint32_t smem_u32(const void* p) {
    uint32_t a;
    asm("{ .reg .u64 t; cvta.to.shared.u64 t, %1; cvt.u32.u64 %0, t; }" : "=r"(a) : "l"(p));
    return a;
}

__global__ __launch_bounds__(256, 2)
void conv_mma_kernel(float* __restrict__ y) {
    extern __shared__ unsigned short sm[];
    const uint32_t smb = smem_u32(sm);

    const int tid = threadIdx.x;
    const int wid = tid >> 5, lane = tid & 31;
    const int gr = lane >> 2, tig = lane & 3;
    const int wm = wid & 3;        // warp h-row
    const int wn = wid >> 2;       // warp oc half

    const int h0 = blockIdx.x * 4;
    const int oc0 = blockIdx.y * 128;
    const int b = blockIdx.z;

    // ---- ldmatrix lane address components ----
    const int r16 = ((lane >> 3) & 1) * 8 + (lane & 7);
    const int kq8 = (lane >> 4) * 8;                       // A: k +8 halves for m2/m3
    int aoff0 = ((wm + 1) * 34 + r16 + 1) * PAD_A + kq8;   // mt=0; mt=1: +16*PAD_A
    const int rb = (lane & 7) + ((lane >> 4) & 1) * 8;
    const int kb8 = ((lane >> 3) & 1) * 8;
    const int boff = (wn * 64 + rb) * PAD_B + kb8;         // + np*16*PAD_B + ks*16

    // ---- A halo loader coords (204 positions) ----
    const int p = tid;
    const bool pa = p < 204;
    const int hi_ = p / 34, wi_ = p % 34;
    const int ha = h0 + hi_ - 1, wa = wi_ - 1;
    const bool va = pa && ((unsigned)ha < HH) && ((unsigned)wa < WW);
    const size_t aidx = (((size_t)b * HH + (va ? ha : 0)) * WW + (va ? wa : 0)) * IC;
    const uint32_t adst_h = smb + (uint32_t)(A_HI_O + p * PAD_A) * 2;
    const uint32_t adst_l = smb + (uint32_t)(A_LO_O + p * PAD_A) * 2;

    // ---- B loader coords ----
    const int rB = tid >> 1, halfB = tid & 1;
    const size_t bRowBase = (size_t)(oc0 + rB) * IC + halfB * 16;

    float acc[2][8][4];
    #pragma unroll
    for (int mt = 0; mt < 2; mt++)
        #pragma unroll
        for (int nt = 0; nt < 8; nt++)
            #pragma unroll
            for (int q = 0; q < 4; q++) acc[mt][nt][q] = 0.f;

    for (int cc = 0; cc < 16; cc++) {
        const int ic0 = cc * KC;
        __syncthreads();   // protect halo A + B buf0 from previous chunk's compute

        // A halo: 4x16B hi + 4x16B lo per position (zfill for OOB)
        if (pa) {
            #pragma unroll
            for (int j = 0; j < 4; j++) {
                cp16(adst_h + j * 16, g_xm_hi + aidx + ic0 + j * 8, va);
                cp16(adst_l + j * 16, g_xm_lo + aidx + ic0 + j * 8, va);
            }
        }
        // B tap 0 -> buf 0
        {
            const size_t src = bRowBase + ic0;   // kk = 0
            uint32_t dh_ = smb + (uint32_t)(B_O(0) + rB * PAD_B + halfB * 16) * 2;
            uint32_t dl_ = dh_ + B_ARR * 2;
            cp16(dh_,      g_wq_hi + src, true);
            cp16(dh_ + 16, g_wq_hi + src + 8, true);
            cp16(dl_,      g_wq_lo + src, true);
            cp16(dl_ + 16, g_wq_lo + src + 8, true);
        }
        CP_COMMIT();

        #pragma unroll
        for (int kk = 0; kk < 9; kk++) {
            CP_WAIT0();
            __syncthreads();
            if (kk < 8) {   // prefetch next tap into other buffer
                const size_t src = (size_t)(kk + 1) * OC * IC + bRowBase + ic0;
                uint32_t dh_ = smb + (uint32_t)(B_O((kk + 1) & 1) + rB * PAD_B + halfB * 16) * 2;
                uint32_t dl_ = dh_ + B_ARR * 2;
                cp16(dh_,      g_wq_hi + src, true);
                cp16(dh_ + 16, g_wq_hi + src + 8, true);
                cp16(dl_,      g_wq_lo + src, true);
                cp16(dl_ + 16, g_wq_lo + src + 8, true);
                CP_COMMIT();
            }

            // ---- compute tap kk from buf kk&1 ----
            const int dh = kk / 3 - 1, dw = kk % 3 - 1;
            const int tsh = (dh * 34 + dw) * PAD_A;
            const uint32_t bbase = smb + (uint32_t)(B_O(kk & 1) + boff) * 2;

            #pragma unroll
            for (int ks = 0; ks < 2; ks++) {
                uint32_t ah[2][4], al[2][4];
                #pragma unroll
                for (int mt = 0; mt < 2; mt++) {
                    uint32_t aa = smb + (uint32_t)(aoff0 + mt * 16 * PAD_A + tsh + ks * 16) * 2;
                    ldsm4(ah[mt], aa);
                    ldsm4(al[mt], aa + A_LO_O * 2);
                }
                #pragma unroll
                for (int np = 0; np < 4; np++) {
                    uint32_t bh[4], bl[4];
                    uint32_t ba = bbase + (uint32_t)(np * 16 * PAD_B + ks * 16) * 2;
                    ldsm4(bh, ba);
                    ldsm4(bl, ba + B_ARR * 2);
                    #pragma unroll
                    for (int mt = 0; mt < 2; mt++) {
                        mma_bf16(acc[mt][2 * np],     ah[mt], bh[0], bh[1]);
                        mma_bf16(acc[mt][2 * np],     ah[mt], bl[0], bl[1]);
                        mma_bf16(acc[mt][2 * np],     al[mt], bh[0], bh[1]);
                        mma_bf16(acc[mt][2 * np + 1], ah[mt], bh[2], bh[3]);
                        mma_bf16(acc[mt][2 * np + 1], ah[mt], bl[2], bl[3]);
                        mma_bf16(acc[mt][2 * np + 1], al[mt], bh[2], bh[3]);
                    }
                }
            }
        }
    }

    // ---- epilogue: demodulate + store ----
    const int h = h0 + wm;
    float scl[8][2];
    #pragma unroll
    for (int nt = 0; nt < 8; nt++) {
        int oc = oc0 + wn * 64 + nt * 8 + tig * 2;
        scl[nt][0] = g_scale[b * OC + oc];
        scl[nt][1] = g_scale[b * OC + oc + 1];
    }
    #pragma unroll
    for (int mt = 0; mt < 2; mt++) {
        int w0 = mt * 16 + gr;
        #pragma unroll
        for (int nt = 0; nt < 8; nt++) {
            int oc = oc0 + wn * 64 + nt * 8 + tig * 2;
            size_t base0 = (((size_t)b * OC + oc) * HH + h) * WW;
            size_t base1 = base0 + (size_t)HH * WW;
            y[base0 + w0]     = acc[mt][nt][0] * scl[nt][0];
            y[base1 + w0]     = acc[mt][nt][1] * scl[nt][1];
            y[base0 + w0 + 8] = acc[mt][nt][2] * scl[nt][0];
            y[base1 + w0 + 8] = acc[mt][nt][3] * scl[nt][1];
        }
    }
}

// ---------------------------------------------------------------------------
extern "C" void kernel_launch(void* const* d_in, const int* in_sizes, int n_in,
                              void* d_out, int out_size) {
    const float* x       = (const float*)d_in[0];
    const float* w       = (const float*)d_in[1];
    const float* conv_w  = (const float*)d_in[2];
    const float* dense_w = (const float*)d_in[3];
    const float* dense_b = (const float*)d_in[4];
    float* y = (float*)d_out;

    style_kernel<<<BN, 256>>>(w, dense_w, dense_b);
    ss_kernel<<<(IC * OC) / 256, 256>>>(conv_w);
    demod_kernel<<<BN, 512>>>();
    wtrans_kernel<<<dim3(IC / 32, OC / 32, 9), 256>>>(conv_w);
    xtrans_kernel<<<dim3(IC / 32, HH, BN), 256>>>(x);

    static bool attr_set = false;
    if (!attr_set) {
        cudaFuncSetAttribute(conv_mma_kernel,
                             cudaFuncAttributeMaxDynamicSharedMemorySize, SM_HALVES * 2);
        attr_set = true;
    }
    conv_mma_kernel<<<dim3(8, 4, BN), 256, SM_HALVES * 2>>>(y);
}

// round 7
// speedup vs baseline: 2.4785x; 1.0646x over previous
#include <cuda_runtime.h>
#include <cuda_bf16.h>
#include <cstdint>

#define BN 8
#define IC 512
#define OC 512
#define HH 32
#define WW 32

#define RC_DENSE 0.04419417382415922f     // 1/sqrt(512)
#define RC_CONV  0.014731391274719739f    // 1/sqrt(9*512)

// ---------------- device scratch (no runtime allocation) ----------------
__device__ float g_style[BN * IC];
__device__ float g_scale[BN * OC];
__device__ float g_ss[IC * OC];
// weights transposed to [tap][oc][ic], split hi/lo bf16
__device__ __align__(128) __nv_bfloat16 g_wq_hi[9 * OC * IC];
__device__ __align__(128) __nv_bfloat16 g_wq_lo[9 * OC * IC];
// modulated input in NHWC: [b][h][w][ic], split hi/lo bf16
__device__ __align__(128) __nv_bfloat16 g_xm_hi[BN * HH * WW * IC];
__device__ __align__(128) __nv_bfloat16 g_xm_lo[BN * HH * WW * IC];

// ---------------- prologue kernels ----------------
__global__ void style_kernel(const float* __restrict__ w,
                             const float* __restrict__ dense_w,
                             const float* __restrict__ dense_b) {
    __shared__ float wrow[IC];
    int b = blockIdx.x;
    for (int j = threadIdx.x; j < IC; j += blockDim.x) wrow[j] = w[b * IC + j];
    __syncthreads();
    for (int i = threadIdx.x; i < IC; i += blockDim.x) {
        float acc = 0.f;
        #pragma unroll 8
        for (int j = 0; j < IC; j++) acc = fmaf(wrow[j], dense_w[j * IC + i], acc);
        g_style[b * IC + i] = RC_DENSE * acc + dense_b[i] + 1.0f;
    }
}

__global__ void ss_kernel(const float* __restrict__ conv_w) {
    int idx = blockIdx.x * blockDim.x + threadIdx.x;
    if (idx >= IC * OC) return;
    float s = 0.f;
    #pragma unroll
    for (int k = 0; k < 9; k++) {
        float v = conv_w[k * IC * OC + idx];
        s = fmaf(v, v, s);
    }
    g_ss[idx] = s;
}

__global__ void demod_kernel() {
    __shared__ float s2[IC];
    int b = blockIdx.x;
    for (int i = threadIdx.x; i < IC; i += blockDim.x) {
        float s = g_style[b * IC + i];
        s2[i] = s * s;
    }
    __syncthreads();
    for (int oc = threadIdx.x; oc < OC; oc += blockDim.x) {
        float acc = 0.f;
        #pragma unroll 8
        for (int i = 0; i < IC; i++) acc = fmaf(s2[i], g_ss[i * OC + oc], acc);
        g_scale[b * OC + oc] = RC_CONV * rsqrtf(RC_CONV * RC_CONV * acc + 1e-8f);
    }
}

// conv_w[k][ic][oc] -> wq[k][oc][ic] (hi/lo bf16)
__global__ void wtrans_kernel(const float* __restrict__ conv_w) {
    __shared__ float tile[32][33];
    int ic0 = blockIdx.x * 32, oc0 = blockIdx.y * 32, k = blockIdx.z;
    int t = threadIdx.x, col = t & 31, row0 = t >> 5;
    #pragma unroll
    for (int rr = 0; rr < 4; rr++) {
        int i = rr * 8 + row0;  // ic
        tile[i][col] = conv_w[((size_t)(k * IC + ic0 + i)) * OC + oc0 + col];
    }
    __syncthreads();
    int r = t >> 3, pp = t & 7;  // r = oc row within tile
    size_t base = ((size_t)(k * OC + oc0 + r)) * IC + ic0;
    #pragma unroll
    for (int it = 0; it < 2; it++) {
        int ci = 2 * (it * 8 + pp);
        float v0 = tile[ci][r], v1 = tile[ci + 1][r];
        __nv_bfloat16 h0 = __float2bfloat16(v0), h1 = __float2bfloat16(v1);
        __nv_bfloat16 l0 = __float2bfloat16(v0 - __bfloat162float(h0));
        __nv_bfloat16 l1 = __float2bfloat16(v1 - __bfloat162float(h1));
        *(__nv_bfloat162*)(g_wq_hi + base + ci) = __halves2bfloat162(h0, h1);
        *(__nv_bfloat162*)(g_wq_lo + base + ci) = __halves2bfloat162(l0, l1);
    }
}

// x[b][ic][h][w] * style[b][ic] -> xm[b][h][w][ic] (hi/lo bf16)
__global__ void xtrans_kernel(const float* __restrict__ x) {
    __shared__ float tile[32][33];
    int ic0 = blockIdx.x * 32, h = blockIdx.y, b = blockIdx.z;
    int t = threadIdx.x, col = t & 31, row0 = t >> 5;
    #pragma unroll
    for (int rr = 0; rr < 4; rr++) {
        int i = rr * 8 + row0;  // ic
        tile[i][col] = x[(((size_t)b * IC + ic0 + i) * HH + h) * WW + col] * g_style[b * IC + ic0 + i];
    }
    __syncthreads();
    int w = t >> 3, pp = t & 7;
    size_t base = (((size_t)b * HH + h) * WW + w) * IC + ic0;
    #pragma unroll
    for (int it = 0; it < 2; it++) {
        int ci = 2 * (it * 8 + pp);
        float v0 = tile[ci][w], v1 = tile[ci + 1][w];
        __nv_bfloat16 h0 = __float2bfloat16(v0), h1 = __float2bfloat16(v1);
        __nv_bfloat16 l0 = __float2bfloat16(v0 - __bfloat162float(h0));
        __nv_bfloat16 l1 = __float2bfloat16(v1 - __bfloat162float(h1));
        *(__nv_bfloat162*)(g_xm_hi + base + ci) = __halves2bfloat162(h0, h1);
        *(__nv_bfloat162*)(g_xm_lo + base + ci) = __halves2bfloat162(l0, l1);
    }
}

// ---------------- main mma.sync conv kernel ----------------
// CTA tile: M=128 (4 h x 32 w) x N=128 oc. 8 warps (4 M x 2 N), warp 32x64.
// A staged once per ic-chunk as 6x34 halo; B(tap) 3-stage cp.async pipeline
// (prefetch depth 2). MMA issue reordered term-major: same-accumulator
// distance 4 to break HMMA RAW chains.
#define KC 32
#define PAD_A 40
#define PAD_B 40

// smem offsets in halves
#define A_HI_O 0
#define A_LO_O 8160
#define B_ARR  5120
#define B_O(buf) (16320 + (buf) * 10240)
#define SM_HALVES 47040      // 94080 bytes

__device__ __forceinline__ void mma_bf16(float* c,
                                         const uint32_t* a, uint32_t b0, uint32_t b1) {
    asm volatile(
        "mma.sync.aligned.m16n8k16.row.col.f32.bf16.bf16.f32 "
        "{%0,%1,%2,%3}, {%4,%5,%6,%7}, {%8,%9}, {%0,%1,%2,%3};"
        : "+f"(c[0]), "+f"(c[1]), "+f"(c[2]), "+f"(c[3])
        : "r"(a[0]), "r"(a[1]), "r"(a[2]), "r"(a[3]), "r"(b0), "r"(b1));
}

__device__ __forceinline__ void ldsm4(uint32_t* r, uint32_t a) {
    asm volatile("ldmatrix.sync.aligned.m8n8.x4.shared.b16 {%0,%1,%2,%3}, [%4];"
                 : "=r"(r[0]), "=r"(r[1]), "=r"(r[2]), "=r"(r[3]) : "r"(a));
}

__device__ __forceinline__ void cp16(uint32_t dst, const void* src, bool v) {
    asm volatile("cp.async.ca.shared.global [%0], [%1], 16, %2;"
                 :: "r"(dst), "l"(src), "r"(v ? 16 : 0) : "memory");
}
#define CP_COMMIT() asm volatile("cp.async.commit_group;" ::: "memory")
#define CP_WAIT0()  asm volatile("cp.async.wait_group 0;" ::: "memory")
#define CP_WAIT1()  asm volatile("cp.async.wait_group 1;" ::: "memory")

__device__ __forceinline__ uint32_t smem_u32(const void* p) {
    uint32_t a;
    asm("{ .reg .u64 t; cvta.to.shared.u64 t, %1; cvt.u32.u64 %0, t; }" : "=r"(a) : "l"(p));
    return a;
}

__global__ __launch_bounds__(256, 2)
void conv_mma_kernel(float* __restrict__ y) {
    extern __shared__ unsigned short sm[];
    const uint32_t smb = smem_u32(sm);

    const int tid = threadIdx.x;
    const int wid = tid >> 5, lane = tid & 31;
    const int gr = lane >> 2, tig = lane & 3;
    const int wm = wid & 3;        // warp h-row
    const int wn = wid >> 2;       // warp oc half

    const int h0 = blockIdx.x * 4;
    const int oc0 = blockIdx.y * 128;
    const int b = blockIdx.z;

    // ---- ldmatrix lane address components ----
    const int r16 = ((lane >> 3) & 1) * 8 + (lane & 7);
    const int kq8 = (lane >> 4) * 8;
    int aoff0 = ((wm + 1) * 34 + r16 + 1) * PAD_A + kq8;
    const int rb = (lane & 7) + ((lane >> 4) & 1) * 8;
    const int kb8 = ((lane >> 3) & 1) * 8;
    const int boff = (wn * 64 + rb) * PAD_B + kb8;

    // ---- A halo loader coords (204 positions) ----
    const int p = tid;
    const bool pa = p < 204;
    const int hi_ = p / 34, wi_ = p % 34;
    const int ha = h0 + hi_ - 1, wa = wi_ - 1;
    const bool va = pa && ((unsigned)ha < HH) && ((unsigned)wa < WW);
    const size_t aidx = (((size_t)b * HH + (va ? ha : 0)) * WW + (va ? wa : 0)) * IC;
    const uint32_t adst_h = smb + (uint32_t)(A_HI_O + p * PAD_A) * 2;
    const uint32_t adst_l = smb + (uint32_t)(A_LO_O + p * PAD_A) * 2;

    // ---- B loader coords ----
    const int rB = tid >> 1, halfB = tid & 1;
    const size_t bRowBase = (size_t)(oc0 + rB) * IC + halfB * 16;
    const uint32_t bdst = (uint32_t)(rB * PAD_B + halfB * 16) * 2;

    float acc[2][8][4];
    #pragma unroll
    for (int mt = 0; mt < 2; mt++)
        #pragma unroll
        for (int nt = 0; nt < 8; nt++)
            #pragma unroll
            for (int q = 0; q < 4; q++) acc[mt][nt][q] = 0.f;

    for (int cc = 0; cc < 16; cc++) {
        const int ic0 = cc * KC;
        __syncthreads();   // protect A halo + B buffers from previous chunk's readers

        // group 0: A halo + B tap0 -> buf0
        if (pa) {
            #pragma unroll
            for (int j = 0; j < 4; j++) {
                cp16(adst_h + j * 16, g_xm_hi + aidx + ic0 + j * 8, va);
                cp16(adst_l + j * 16, g_xm_lo + aidx + ic0 + j * 8, va);
            }
        }
        {
            const size_t src = bRowBase + ic0;
            uint32_t dh_ = smb + (uint32_t)B_O(0) * 2 + bdst;
            uint32_t dl_ = dh_ + B_ARR * 2;
            cp16(dh_,      g_wq_hi + src, true);
            cp16(dh_ + 16, g_wq_hi + src + 8, true);
            cp16(dl_,      g_wq_lo + src, true);
            cp16(dl_ + 16, g_wq_lo + src + 8, true);
        }
        CP_COMMIT();
        // group 1: B tap1 -> buf1
        {
            const size_t src = (size_t)OC * IC + bRowBase + ic0;
            uint32_t dh_ = smb + (uint32_t)B_O(1) * 2 + bdst;
            uint32_t dl_ = dh_ + B_ARR * 2;
            cp16(dh_,      g_wq_hi + src, true);
            cp16(dh_ + 16, g_wq_hi + src + 8, true);
            cp16(dl_,      g_wq_lo + src, true);
            cp16(dl_ + 16, g_wq_lo + src + 8, true);
        }
        CP_COMMIT();

        #pragma unroll
        for (int kk = 0; kk < 9; kk++) {
            if (kk < 7) { CP_WAIT1(); } else { CP_WAIT0(); }
            __syncthreads();
            if (kk < 7) {   // prefetch tap kk+2 -> buf (kk+2)%3
                const size_t src = (size_t)(kk + 2) * OC * IC + bRowBase + ic0;
                uint32_t dh_ = smb + (uint32_t)B_O((kk + 2) % 3) * 2 + bdst;
                uint32_t dl_ = dh_ + B_ARR * 2;
                cp16(dh_,      g_wq_hi + src, true);
                cp16(dh_ + 16, g_wq_hi + src + 8, true);
                cp16(dl_,      g_wq_lo + src, true);
                cp16(dl_ + 16, g_wq_lo + src + 8, true);
                CP_COMMIT();
            }

            // ---- compute tap kk from buf kk%3 ----
            const int dh = kk / 3 - 1, dw = kk % 3 - 1;
            const int tsh = (dh * 34 + dw) * PAD_A;
            const uint32_t bbase = smb + (uint32_t)(B_O(kk % 3) + boff) * 2;

            #pragma unroll
            for (int ks = 0; ks < 2; ks++) {
                uint32_t ah[2][4], al[2][4];
                #pragma unroll
                for (int mt = 0; mt < 2; mt++) {
                    uint32_t aa = smb + (uint32_t)(aoff0 + mt * 16 * PAD_A + tsh + ks * 16) * 2;
                    ldsm4(ah[mt], aa);
                    ldsm4(al[mt], aa + A_LO_O * 2);
                }
                #pragma unroll
                for (int np = 0; np < 4; np++) {
                    uint32_t bh[4], bl[4];
                    uint32_t ba = bbase + (uint32_t)(np * 16 * PAD_B + ks * 16) * 2;
                    ldsm4(bh, ba);
                    ldsm4(bl, ba + B_ARR * 2);
                    // term-major issue: same-accumulator distance = 4
                    mma_bf16(acc[0][2 * np],     ah[0], bh[0], bh[1]);
                    mma_bf16(acc[1][2 * np],     ah[1], bh[0], bh[1]);
                    mma_bf16(acc[0][2 * np + 1], ah[0], bh[2], bh[3]);
                    mma_bf16(acc[1][2 * np + 1], ah[1], bh[2], bh[3]);

                    mma_bf16(acc[0][2 * np],     ah[0], bl[0], bl[1]);
                    mma_bf16(acc[1][2 * np],     ah[1], bl[0], bl[1]);
                    mma_bf16(acc[0][2 * np + 1], ah[0], bl[2], bl[3]);
                    mma_bf16(acc[1][2 * np + 1], ah[1], bl[2], bl[3]);

                    mma_bf16(acc[0][2 * np],     al[0], bh[0], bh[1]);
                    mma_bf16(acc[1][2 * np],     al[1], bh[0], bh[1]);
                    mma_bf16(acc[0][2 * np + 1], al[0], bh[2], bh[3]);
                    mma_bf16(acc[1][2 * np + 1], al[1], bh[2], bh[3]);
                }
            }
        }
    }

    // ---- epilogue: demodulate + store ----
    const int h = h0 + wm;
    float scl[8][2];
    #pragma unroll
    for (int nt = 0; nt < 8; nt++) {
        int oc = oc0 + wn * 64 + nt * 8 + tig * 2;
        scl[nt][0] = g_scale[b * OC + oc];
        scl[nt][1] = g_scale[b * OC + oc + 1];
    }
    #pragma unroll
    for (int mt = 0; mt < 2; mt++) {
        int w0 = mt * 16 + gr;
        #pragma unroll
        for (int nt = 0; nt < 8; nt++) {
            int oc = oc0 + wn * 64 + nt * 8 + tig * 2;
            size_t base0 = (((size_t)b * OC + oc) * HH + h) * WW;
            size_t base1 = base0 + (size_t)HH * WW;
            y[base0 + w0]     = acc[mt][nt][0] * scl[nt][0];
            y[base1 + w0]     = acc[mt][nt][1] * scl[nt][1];
            y[base0 + w0 + 8] = acc[mt][nt][2] * scl[nt][0];
            y[base1 + w0 + 8] = acc[mt][nt][3] * scl[nt][1];
        }
    }
}

// ---------------------------------------------------------------------------
extern "C" void kernel_launch(void* const* d_in, const int* in_sizes, int n_in,
                              void* d_out, int out_size) {
    const float* x       = (const float*)d_in[0];
    const float* w       = (const float*)d_in[1];
    const float* conv_w  = (const float*)d_in[2];
    const float* dense_w = (const float*)d_in[3];
    const float* dense_b = (const float*)d_in[4];
    float* y = (float*)d_out;

    style_kernel<<<BN, 256>>>(w, dense_w, dense_b);
    ss_kernel<<<(IC * OC) / 256, 256>>>(conv_w);
    demod_kernel<<<BN, 512>>>();
    wtrans_kernel<<<dim3(IC / 32, OC / 32, 9), 256>>>(conv_w);
    xtrans_kernel<<<dim3(IC / 32, HH, BN), 256>>>(x);

    static bool attr_set = false;
    if (!attr_set) {
        cudaFuncSetAttribute(conv_mma_kernel,
                             cudaFuncAttributeMaxDynamicSharedMemorySize, SM_HALVES * 2);
        attr_set = true;
    }
    conv_mma_kernel<<<dim3(8, 4, BN), 256, SM_HALVES * 2>>>(y);
}

// round 8
// speedup vs baseline: 3.4944x; 1.4099x over previous
#include <cuda_runtime.h>
#include <cuda_fp16.h>
#include <cstdint>

#define BN 8
#define IC 512
#define OC 512
#define HH 32
#define WW 32

#define RC_DENSE 0.04419417382415922f     // 1/sqrt(512)
#define RC_CONV  0.014731391274719739f    // 1/sqrt(9*512)

// ---------------- device scratch (no runtime allocation) ----------------
__device__ float g_style[BN * IC];
__device__ float g_scale[BN * OC];
__device__ float g_ss[IC * OC];
// weights transposed to [tap][oc][ic], single fp16
__device__ __align__(128) __half g_wq[9 * OC * IC];
// modulated input in NHWC: [b][h][w][ic], split hi/lo fp16
__device__ __align__(128) __half g_xm_hi[BN * HH * WW * IC];
__device__ __align__(128) __half g_xm_lo[BN * HH * WW * IC];

// ---------------- prologue kernels ----------------
__global__ void style_kernel(const float* __restrict__ w,
                             const float* __restrict__ dense_w,
                             const float* __restrict__ dense_b) {
    __shared__ float wrow[IC];
    int b = blockIdx.x;
    for (int j = threadIdx.x; j < IC; j += blockDim.x) wrow[j] = w[b * IC + j];
    __syncthreads();
    for (int i = threadIdx.x; i < IC; i += blockDim.x) {
        float acc = 0.f;
        #pragma unroll 8
        for (int j = 0; j < IC; j++) acc = fmaf(wrow[j], dense_w[j * IC + i], acc);
        g_style[b * IC + i] = RC_DENSE * acc + dense_b[i] + 1.0f;
    }
}

__global__ void ss_kernel(const float* __restrict__ conv_w) {
    int idx = blockIdx.x * blockDim.x + threadIdx.x;
    if (idx >= IC * OC) return;
    float s = 0.f;
    #pragma unroll
    for (int k = 0; k < 9; k++) {
        float v = conv_w[k * IC * OC + idx];
        s = fmaf(v, v, s);
    }
    g_ss[idx] = s;
}

__global__ void demod_kernel() {
    __shared__ float s2[IC];
    int b = blockIdx.x;
    for (int i = threadIdx.x; i < IC; i += blockDim.x) {
        float s = g_style[b * IC + i];
        s2[i] = s * s;
    }
    __syncthreads();
    for (int oc = threadIdx.x; oc < OC; oc += blockDim.x) {
        float acc = 0.f;
        #pragma unroll 8
        for (int i = 0; i < IC; i++) acc = fmaf(s2[i], g_ss[i * OC + oc], acc);
        g_scale[b * OC + oc] = RC_CONV * rsqrtf(RC_CONV * RC_CONV * acc + 1e-8f);
    }
}

// conv_w[k][ic][oc] -> wq[k][oc][ic] (single fp16)
__global__ void wtrans_kernel(const float* __restrict__ conv_w) {
    __shared__ float tile[32][33];
    int ic0 = blockIdx.x * 32, oc0 = blockIdx.y * 32, k = blockIdx.z;
    int t = threadIdx.x, col = t & 31, row0 = t >> 5;
    #pragma unroll
    for (int rr = 0; rr < 4; rr++) {
        int i = rr * 8 + row0;  // ic
        tile[i][col] = conv_w[((size_t)(k * IC + ic0 + i)) * OC + oc0 + col];
    }
    __syncthreads();
    int r = t >> 3, pp = t & 7;  // r = oc row within tile
    size_t base = ((size_t)(k * OC + oc0 + r)) * IC + ic0;
    #pragma unroll
    for (int it = 0; it < 2; it++) {
        int ci = 2 * (it * 8 + pp);
        float v0 = tile[ci][r], v1 = tile[ci + 1][r];
        *(__half2*)(g_wq + base + ci) =
            __halves2half2(__float2half_rn(v0), __float2half_rn(v1));
    }
}

// x[b][ic][h][w] * style[b][ic] -> xm[b][h][w][ic] (hi/lo fp16)
__global__ void xtrans_kernel(const float* __restrict__ x) {
    __shared__ float tile[32][33];
    int ic0 = blockIdx.x * 32, h = blockIdx.y, b = blockIdx.z;
    int t = threadIdx.x, col = t & 31, row0 = t >> 5;
    #pragma unroll
    for (int rr = 0; rr < 4; rr++) {
        int i = rr * 8 + row0;  // ic
        tile[i][col] = x[(((size_t)b * IC + ic0 + i) * HH + h) * WW + col] * g_style[b * IC + ic0 + i];
    }
    __syncthreads();
    int w = t >> 3, pp = t & 7;
    size_t base = (((size_t)b * HH + h) * WW + w) * IC + ic0;
    #pragma unroll
    for (int it = 0; it < 2; it++) {
        int ci = 2 * (it * 8 + pp);
        float v0 = tile[ci][w], v1 = tile[ci + 1][w];
        __half h0 = __float2half_rn(v0), h1 = __float2half_rn(v1);
        __half l0 = __float2half_rn(v0 - __half2float(h0));
        __half l1 = __float2half_rn(v1 - __half2float(h1));
        *(__half2*)(g_xm_hi + base + ci) = __halves2half2(h0, h1);
        *(__half2*)(g_xm_lo + base + ci) = __halves2half2(l0, l1);
    }
}

// ---------------- main mma.sync conv kernel ----------------
// CTA tile: M=128 (4 h x 32 w) x N=128 oc. 8 warps (4 M x 2 N), warp 32x64.
// A staged once per ic-chunk as 6x34 halo (fp16 hi+lo); B(tap) single fp16,
// 3-stage cp.async pipeline (prefetch depth 2). 2-term MMA:
//   acc += Ah*B + Al*B  (exact A, fp16-quantized B -> rel err ~1e-4)
#define KC 32
#define PAD_A 40
#define PAD_B 40

// smem offsets in halves
#define A_HI_O 0
#define A_LO_O 8160
#define B_O(buf) (16320 + (buf) * 5120)
#define SM_HALVES 31680      // 63360 bytes

__device__ __forceinline__ void mma_f16(float* c,
                                        const uint32_t* a, uint32_t b0, uint32_t b1) {
    asm volatile(
        "mma.sync.aligned.m16n8k16.row.col.f32.f16.f16.f32 "
        "{%0,%1,%2,%3}, {%4,%5,%6,%7}, {%8,%9}, {%0,%1,%2,%3};"
        : "+f"(c[0]), "+f"(c[1]), "+f"(c[2]), "+f"(c[3])
        : "r"(a[0]), "r"(a[1]), "r"(a[2]), "r"(a[3]), "r"(b0), "r"(b1));
}

__device__ __forceinline__ void ldsm4(uint32_t* r, uint32_t a) {
    asm volatile("ldmatrix.sync.aligned.m8n8.x4.shared.b16 {%0,%1,%2,%3}, [%4];"
                 : "=r"(r[0]), "=r"(r[1]), "=r"(r[2]), "=r"(r[3]) : "r"(a));
}

__device__ __forceinline__ void cp16(uint32_t dst, const void* src, bool v) {
    asm volatile("cp.async.ca.shared.global [%0], [%1], 16, %2;"
                 :: "r"(dst), "l"(src), "r"(v ? 16 : 0) : "memory");
}
#define CP_COMMIT() asm volatile("cp.async.commit_group;" ::: "memory")
#define CP_WAIT0()  asm volatile("cp.async.wait_group 0;" ::: "memory")
#define CP_WAIT1()  asm volatile("cp.async.wait_group 1;" ::: "memory")

__device__ __forceinline__ uint32_t smem_u32(const void* p) {
    uint32_t a;
    asm("{ .reg .u64 t; cvta.to.shared.u64 t, %1; cvt.u32.u64 %0, t; }" : "=r"(a) : "l"(p));
    return a;
}

__global__ __launch_bounds__(256, 2)
void conv_mma_kernel(float* __restrict__ y) {
    extern __shared__ unsigned short sm[];
    const uint32_t smb = smem_u32(sm);

    const int tid = threadIdx.x;
    const int wid = tid >> 5, lane = tid & 31;
    const int gr = lane >> 2, tig = lane & 3;
    const int wm = wid & 3;        // warp h-row
    const int wn = wid >> 2;       // warp oc half

    const int h0 = blockIdx.x * 4;
    const int oc0 = blockIdx.y * 128;
    const int b = blockIdx.z;

    // ---- ldmatrix lane address components ----
    const int r16 = ((lane >> 3) & 1) * 8 + (lane & 7);
    const int kq8 = (lane >> 4) * 8;
    int aoff0 = ((wm + 1) * 34 + r16 + 1) * PAD_A + kq8;
    const int rb = (lane & 7) + ((lane >> 4) & 1) * 8;
    const int kb8 = ((lane >> 3) & 1) * 8;
    const int boff = (wn * 64 + rb) * PAD_B + kb8;

    // ---- A halo loader coords (204 positions) ----
    const int p = tid;
    const bool pa = p < 204;
    const int hi_ = p / 34, wi_ = p % 34;
    const int ha = h0 + hi_ - 1, wa = wi_ - 1;
    const bool va = pa && ((unsigned)ha < HH) && ((unsigned)wa < WW);
    const size_t aidx = (((size_t)b * HH + (va ? ha : 0)) * WW + (va ? wa : 0)) * IC;
    const uint32_t adst_h = smb + (uint32_t)(A_HI_O + p * PAD_A) * 2;
    const uint32_t adst_l = smb + (uint32_t)(A_LO_O + p * PAD_A) * 2;

    // ---- B loader coords (2 x 16B per thread covers 128 rows x 32 halves) ----
    const int rB = tid >> 1, halfB = tid & 1;
    const size_t bRowBase = (size_t)(oc0 + rB) * IC + halfB * 16;
    const uint32_t bdst = (uint32_t)(rB * PAD_B + halfB * 16) * 2;

    float acc[2][8][4];
    #pragma unroll
    for (int mt = 0; mt < 2; mt++)
        #pragma unroll
        for (int nt = 0; nt < 8; nt++)
            #pragma unroll
            for (int q = 0; q < 4; q++) acc[mt][nt][q] = 0.f;

    for (int cc = 0; cc < 16; cc++) {
        const int ic0 = cc * KC;
        __syncthreads();   // protect A halo + B buffers from previous chunk's readers

        // group 0: A halo + B tap0 -> buf0
        if (pa) {
            #pragma unroll
            for (int j = 0; j < 4; j++) {
                cp16(adst_h + j * 16, g_xm_hi + aidx + ic0 + j * 8, va);
                cp16(adst_l + j * 16, g_xm_lo + aidx + ic0 + j * 8, va);
            }
        }
        {
            const size_t src = bRowBase + ic0;
            uint32_t d_ = smb + (uint32_t)B_O(0) * 2 + bdst;
            cp16(d_,      g_wq + src, true);
            cp16(d_ + 16, g_wq + src + 8, true);
        }
        CP_COMMIT();
        // group 1: B tap1 -> buf1
        {
            const size_t src = (size_t)OC * IC + bRowBase + ic0;
            uint32_t d_ = smb + (uint32_t)B_O(1) * 2 + bdst;
            cp16(d_,      g_wq + src, true);
            cp16(d_ + 16, g_wq + src + 8, true);
        }
        CP_COMMIT();

        #pragma unroll
        for (int kk = 0; kk < 9; kk++) {
            if (kk < 7) { CP_WAIT1(); } else { CP_WAIT0(); }
            __syncthreads();
            if (kk < 7) {   // prefetch tap kk+2 -> buf (kk+2)%3
                const size_t src = (size_t)(kk + 2) * OC * IC + bRowBase + ic0;
                uint32_t d_ = smb + (uint32_t)B_O((kk + 2) % 3) * 2 + bdst;
                cp16(d_,      g_wq + src, true);
                cp16(d_ + 16, g_wq + src + 8, true);
                CP_COMMIT();
            }

            // ---- compute tap kk from buf kk%3 ----
            const int dh = kk / 3 - 1, dw = kk % 3 - 1;
            const int tsh = (dh * 34 + dw) * PAD_A;
            const uint32_t bbase = smb + (uint32_t)(B_O(kk % 3) + boff) * 2;

            #pragma unroll
            for (int ks = 0; ks < 2; ks++) {
                uint32_t ah[2][4], al[2][4];
                #pragma unroll
                for (int mt = 0; mt < 2; mt++) {
                    uint32_t aa = smb + (uint32_t)(aoff0 + mt * 16 * PAD_A + tsh + ks * 16) * 2;
                    ldsm4(ah[mt], aa);
                    ldsm4(al[mt], aa + A_LO_O * 2);
                }
                #pragma unroll
                for (int np = 0; np < 4; np++) {
                    uint32_t bh[4];
                    uint32_t ba = bbase + (uint32_t)(np * 16 * PAD_B + ks * 16) * 2;
                    ldsm4(bh, ba);
                    // term-major issue: same-accumulator distance = 4
                    mma_f16(acc[0][2 * np],     ah[0], bh[0], bh[1]);
                    mma_f16(acc[1][2 * np],     ah[1], bh[0], bh[1]);
                    mma_f16(acc[0][2 * np + 1], ah[0], bh[2], bh[3]);
                    mma_f16(acc[1][2 * np + 1], ah[1], bh[2], bh[3]);

                    mma_f16(acc[0][2 * np],     al[0], bh[0], bh[1]);
                    mma_f16(acc[1][2 * np],     al[1], bh[0], bh[1]);
                    mma_f16(acc[0][2 * np + 1], al[0], bh[2], bh[3]);
                    mma_f16(acc[1][2 * np + 1], al[1], bh[2], bh[3]);
                }
            }
        }
    }

    // ---- epilogue: demodulate + store ----
    const int h = h0 + wm;
    float scl[8][2];
    #pragma unroll
    for (int nt = 0; nt < 8; nt++) {
        int oc = oc0 + wn * 64 + nt * 8 + tig * 2;
        scl[nt][0] = g_scale[b * OC + oc];
        scl[nt][1] = g_scale[b * OC + oc + 1];
    }
    #pragma unroll
    for (int mt = 0; mt < 2; mt++) {
        int w0 = mt * 16 + gr;
        #pragma unroll
        for (int nt = 0; nt < 8; nt++) {
            int oc = oc0 + wn * 64 + nt * 8 + tig * 2;
            size_t base0 = (((size_t)b * OC + oc) * HH + h) * WW;
            size_t base1 = base0 + (size_t)HH * WW;
            y[base0 + w0]     = acc[mt][nt][0] * scl[nt][0];
            y[base1 + w0]     = acc[mt][nt][1] * scl[nt][1];
            y[base0 + w0 + 8] = acc[mt][nt][2] * scl[nt][0];
            y[base1 + w0 + 8] = acc[mt][nt][3] * scl[nt][1];
        }
    }
}

// ---------------------------------------------------------------------------
extern "C" void kernel_launch(void* const* d_in, const int* in_sizes, int n_in,
                              void* d_out, int out_size) {
    const float* x       = (const float*)d_in[0];
    const float* w       = (const float*)d_in[1];
    const float* conv_w  = (const float*)d_in[2];
    const float* dense_w = (const float*)d_in[3];
    const float* dense_b = (const float*)d_in[4];
    float* y = (float*)d_out;

    style_kernel<<<BN, 256>>>(w, dense_w, dense_b);
    ss_kernel<<<(IC * OC) / 256, 256>>>(conv_w);
    demod_kernel<<<BN, 512>>>();
    wtrans_kernel<<<dim3(IC / 32, OC / 32, 9), 256>>>(conv_w);
    xtrans_kernel<<<dim3(IC / 32, HH, BN), 256>>>(x);

    static bool attr_set = false;
    if (!attr_set) {
        cudaFuncSetAttribute(conv_mma_kernel,
                             cudaFuncAttributeMaxDynamicSharedMemorySize, SM_HALVES * 2);
        attr_set = true;
    }
    conv_mma_kernel<<<dim3(8, 4, BN), 256, SM_HALVES * 2>>>(y);
}

// round 9
// speedup vs baseline: 4.9558x; 1.4182x over previous
#include <cuda_runtime.h>
#include <cuda_fp16.h>
#include <cstdint>

#define BN 8
#define IC 512
#define OC 512
#define HH 32
#define WW 32

#define RC_DENSE 0.04419417382415922f     // 1/sqrt(512)
#define RC_CONV  0.014731391274719739f    // 1/sqrt(9*512)

// ---------------- device scratch (no runtime allocation) ----------------
__device__ float g_style[BN * IC];
__device__ float g_scale[BN * OC];
__device__ float g_ss[IC * OC];
// weights transposed to [tap][oc][ic], fp16
__device__ __align__(128) __half g_wq[9 * OC * IC];
// modulated input in NHWC: [b][h][w][ic], fp16
__device__ __align__(128) __half g_xm[BN * HH * WW * IC];

// ---------------- prologue kernels ----------------
__global__ void style_kernel(const float* __restrict__ w,
                             const float* __restrict__ dense_w,
                             const float* __restrict__ dense_b) {
    __shared__ float wrow[IC];
    int b = blockIdx.x;
    for (int j = threadIdx.x; j < IC; j += blockDim.x) wrow[j] = w[b * IC + j];
    __syncthreads();
    for (int i = threadIdx.x; i < IC; i += blockDim.x) {
        float acc = 0.f;
        #pragma unroll 8
        for (int j = 0; j < IC; j++) acc = fmaf(wrow[j], dense_w[j * IC + i], acc);
        g_style[b * IC + i] = RC_DENSE * acc + dense_b[i] + 1.0f;
    }
}

__global__ void ss_kernel(const float* __restrict__ conv_w) {
    int idx = blockIdx.x * blockDim.x + threadIdx.x;
    if (idx >= IC * OC) return;
    float s = 0.f;
    #pragma unroll
    for (int k = 0; k < 9; k++) {
        float v = conv_w[k * IC * OC + idx];
        s = fmaf(v, v, s);
    }
    g_ss[idx] = s;
}

__global__ void demod_kernel() {
    __shared__ float s2[IC];
    int b = blockIdx.x;
    for (int i = threadIdx.x; i < IC; i += blockDim.x) {
        float s = g_style[b * IC + i];
        s2[i] = s * s;
    }
    __syncthreads();
    for (int oc = threadIdx.x; oc < OC; oc += blockDim.x) {
        float acc = 0.f;
        #pragma unroll 8
        for (int i = 0; i < IC; i++) acc = fmaf(s2[i], g_ss[i * OC + oc], acc);
        g_scale[b * OC + oc] = RC_CONV * rsqrtf(RC_CONV * RC_CONV * acc + 1e-8f);
    }
}

// conv_w[k][ic][oc] -> wq[k][oc][ic] (fp16)
__global__ void wtrans_kernel(const float* __restrict__ conv_w) {
    __shared__ float tile[32][33];
    int ic0 = blockIdx.x * 32, oc0 = blockIdx.y * 32, k = blockIdx.z;
    int t = threadIdx.x, col = t & 31, row0 = t >> 5;
    #pragma unroll
    for (int rr = 0; rr < 4; rr++) {
        int i = rr * 8 + row0;  // ic
        tile[i][col] = conv_w[((size_t)(k * IC + ic0 + i)) * OC + oc0 + col];
    }
    __syncthreads();
    int r = t >> 3, pp = t & 7;  // r = oc row within tile
    size_t base = ((size_t)(k * OC + oc0 + r)) * IC + ic0;
    #pragma unroll
    for (int it = 0; it < 2; it++) {
        int ci = 2 * (it * 8 + pp);
        *(__half2*)(g_wq + base + ci) =
            __halves2half2(__float2half_rn(tile[ci][r]), __float2half_rn(tile[ci + 1][r]));
    }
}

// x[b][ic][h][w] * style[b][ic] -> xm[b][h][w][ic] (fp16)
__global__ void xtrans_kernel(const float* __restrict__ x) {
    __shared__ float tile[32][33];
    int ic0 = blockIdx.x * 32, h = blockIdx.y, b = blockIdx.z;
    int t = threadIdx.x, col = t & 31, row0 = t >> 5;
    #pragma unroll
    for (int rr = 0; rr < 4; rr++) {
        int i = rr * 8 + row0;  // ic
        tile[i][col] = x[(((size_t)b * IC + ic0 + i) * HH + h) * WW + col] * g_style[b * IC + ic0 + i];
    }
    __syncthreads();
    int w = t >> 3, pp = t & 7;
    size_t base = (((size_t)b * HH + h) * WW + w) * IC + ic0;
    #pragma unroll
    for (int it = 0; it < 2; it++) {
        int ci = 2 * (it * 8 + pp);
        *(__half2*)(g_xm + base + ci) =
            __halves2half2(__float2half_rn(tile[ci][w]), __float2half_rn(tile[ci + 1][w]));
    }
}

// ---------------- main mma.sync conv kernel ----------------
// CTA tile: M=128 (4 h x 32 w) x N=128 oc. 8 warps (4 M x 2 N), warp 32x64.
// A staged once per ic-chunk as 6x34 halo (single fp16); B(tap) fp16,
// 3-stage cp.async pipeline (prefetch depth 2). Single-term fp16 MMA.
#define KC 32
#define PAD_A 40
#define PAD_B 40

// smem offsets in halves
#define A_O 0
#define B_O(buf) (8160 + (buf) * 5120)
#define SM_HALVES 23520      // 47040 bytes

__device__ __forceinline__ void mma_f16(float* c,
                                        const uint32_t* a, uint32_t b0, uint32_t b1) {
    asm volatile(
        "mma.sync.aligned.m16n8k16.row.col.f32.f16.f16.f32 "
        "{%0,%1,%2,%3}, {%4,%5,%6,%7}, {%8,%9}, {%0,%1,%2,%3};"
        : "+f"(c[0]), "+f"(c[1]), "+f"(c[2]), "+f"(c[3])
        : "r"(a[0]), "r"(a[1]), "r"(a[2]), "r"(a[3]), "r"(b0), "r"(b1));
}

__device__ __forceinline__ void ldsm4(uint32_t* r, uint32_t a) {
    asm volatile("ldmatrix.sync.aligned.m8n8.x4.shared.b16 {%0,%1,%2,%3}, [%4];"
                 : "=r"(r[0]), "=r"(r[1]), "=r"(r[2]), "=r"(r[3]) : "r"(a));
}

__device__ __forceinline__ void cp16(uint32_t dst, const void* src, bool v) {
    asm volatile("cp.async.ca.shared.global [%0], [%1], 16, %2;"
                 :: "r"(dst), "l"(src), "r"(v ? 16 : 0) : "memory");
}
#define CP_COMMIT() asm volatile("cp.async.commit_group;" ::: "memory")
#define CP_WAIT0()  asm volatile("cp.async.wait_group 0;" ::: "memory")
#define CP_WAIT1()  asm volatile("cp.async.wait_group 1;" ::: "memory")

__device__ __forceinline__ uint32_t smem_u32(const void* p) {
    uint32_t a;
    asm("{ .reg .u64 t; cvta.to.shared.u64 t, %1; cvt.u32.u64 %0, t; }" : "=r"(a) : "l"(p));
    return a;
}

__global__ __launch_bounds__(256, 2)
void conv_mma_kernel(float* __restrict__ y) {
    extern __shared__ unsigned short sm[];
    const uint32_t smb = smem_u32(sm);

    const int tid = threadIdx.x;
    const int wid = tid >> 5, lane = tid & 31;
    const int gr = lane >> 2, tig = lane & 3;
    const int wm = wid & 3;        // warp h-row
    const int wn = wid >> 2;       // warp oc half

    const int h0 = blockIdx.x * 4;
    const int oc0 = blockIdx.y * 128;
    const int b = blockIdx.z;

    // ---- ldmatrix lane address components ----
    const int r16 = ((lane >> 3) & 1) * 8 + (lane & 7);
    const int kq8 = (lane >> 4) * 8;
    int aoff0 = ((wm + 1) * 34 + r16 + 1) * PAD_A + kq8;
    const int rb = (lane & 7) + ((lane >> 4) & 1) * 8;
    const int kb8 = ((lane >> 3) & 1) * 8;
    const int boff = (wn * 64 + rb) * PAD_B + kb8;

    // ---- A halo loader coords (204 positions) ----
    const int p = tid;
    const bool pa = p < 204;
    const int hi_ = p / 34, wi_ = p % 34;
    const int ha = h0 + hi_ - 1, wa = wi_ - 1;
    const bool va = pa && ((unsigned)ha < HH) && ((unsigned)wa < WW);
    const size_t aidx = (((size_t)b * HH + (va ? ha : 0)) * WW + (va ? wa : 0)) * IC;
    const uint32_t adst = smb + (uint32_t)(A_O + p * PAD_A) * 2;

    // ---- B loader coords ----
    const int rB = tid >> 1, halfB = tid & 1;
    const size_t bRowBase = (size_t)(oc0 + rB) * IC + halfB * 16;
    const uint32_t bdst = (uint32_t)(rB * PAD_B + halfB * 16) * 2;

    float acc[2][8][4];
    #pragma unroll
    for (int mt = 0; mt < 2; mt++)
        #pragma unroll
        for (int nt = 0; nt < 8; nt++)
            #pragma unroll
            for (int q = 0; q < 4; q++) acc[mt][nt][q] = 0.f;

    for (int cc = 0; cc < 16; cc++) {
        const int ic0 = cc * KC;
        __syncthreads();   // protect A halo + B buffers from previous chunk's readers

        // group 0: A halo + B tap0 -> buf0
        if (pa) {
            #pragma unroll
            for (int j = 0; j < 4; j++)
                cp16(adst + j * 16, g_xm + aidx + ic0 + j * 8, va);
        }
        {
            const size_t src = bRowBase + ic0;
            uint32_t d_ = smb + (uint32_t)B_O(0) * 2 + bdst;
            cp16(d_,      g_wq + src, true);
            cp16(d_ + 16, g_wq + src + 8, true);
        }
        CP_COMMIT();
        // group 1: B tap1 -> buf1
        {
            const size_t src = (size_t)OC * IC + bRowBase + ic0;
            uint32_t d_ = smb + (uint32_t)B_O(1) * 2 + bdst;
            cp16(d_,      g_wq + src, true);
            cp16(d_ + 16, g_wq + src + 8, true);
        }
        CP_COMMIT();

        #pragma unroll
        for (int kk = 0; kk < 9; kk++) {
            if (kk < 7) { CP_WAIT1(); } else { CP_WAIT0(); }
            __syncthreads();
            if (kk < 7) {   // prefetch tap kk+2 -> buf (kk+2)%3
                const size_t src = (size_t)(kk + 2) * OC * IC + bRowBase + ic0;
                uint32_t d_ = smb + (uint32_t)B_O((kk + 2) % 3) * 2 + bdst;
                cp16(d_,      g_wq + src, true);
                cp16(d_ + 16, g_wq + src + 8, true);
                CP_COMMIT();
            }

            // ---- compute tap kk from buf kk%3 ----
            const int dh = kk / 3 - 1, dw = kk % 3 - 1;
            const int tsh = (dh * 34 + dw) * PAD_A;
            const uint32_t bbase = smb + (uint32_t)(B_O(kk % 3) + boff) * 2;

            #pragma unroll
            for (int ks = 0; ks < 2; ks++) {
                uint32_t ah[2][4];
                #pragma unroll
                for (int mt = 0; mt < 2; mt++) {
                    uint32_t aa = smb + (uint32_t)(aoff0 + mt * 16 * PAD_A + tsh + ks * 16) * 2;
                    ldsm4(ah[mt], aa);
                }
                #pragma unroll
                for (int np = 0; np < 4; np++) {
                    uint32_t bh[4];
                    uint32_t ba = bbase + (uint32_t)(np * 16 * PAD_B + ks * 16) * 2;
                    ldsm4(bh, ba);
                    // same-accumulator distance = 4
                    mma_f16(acc[0][2 * np],     ah[0], bh[0], bh[1]);
                    mma_f16(acc[1][2 * np],     ah[1], bh[0], bh[1]);
                    mma_f16(acc[0][2 * np + 1], ah[0], bh[2], bh[3]);
                    mma_f16(acc[1][2 * np + 1], ah[1], bh[2], bh[3]);
                }
            }
        }
    }

    // ---- epilogue: demodulate + store ----
    const int h = h0 + wm;
    float scl[8][2];
    #pragma unroll
    for (int nt = 0; nt < 8; nt++) {
        int oc = oc0 + wn * 64 + nt * 8 + tig * 2;
        scl[nt][0] = g_scale[b * OC + oc];
        scl[nt][1] = g_scale[b * OC + oc + 1];
    }
    #pragma unroll
    for (int mt = 0; mt < 2; mt++) {
        int w0 = mt * 16 + gr;
        #pragma unroll
        for (int nt = 0; nt < 8; nt++) {
            int oc = oc0 + wn * 64 + nt * 8 + tig * 2;
            size_t base0 = (((size_t)b * OC + oc) * HH + h) * WW;
            size_t base1 = base0 + (size_t)HH * WW;
            y[base0 + w0]     = acc[mt][nt][0] * scl[nt][0];
            y[base1 + w0]     = acc[mt][nt][1] * scl[nt][1];
            y[base0 + w0 + 8] = acc[mt][nt][2] * scl[nt][0];
            y[base1 + w0 + 8] = acc[mt][nt][3] * scl[nt][1];
        }
    }
}

// ---------------------------------------------------------------------------
extern "C" void kernel_launch(void* const* d_in, const int* in_sizes, int n_in,
                              void* d_out, int out_size) {
    const float* x       = (const float*)d_in[0];
    const float* w       = (const float*)d_in[1];
    const float* conv_w  = (const float*)d_in[2];
    const float* dense_w = (const float*)d_in[3];
    const float* dense_b = (const float*)d_in[4];
    float* y = (float*)d_out;

    style_kernel<<<BN, 256>>>(w, dense_w, dense_b);
    ss_kernel<<<(IC * OC) / 256, 256>>>(conv_w);
    demod_kernel<<<BN, 512>>>();
    wtrans_kernel<<<dim3(IC / 32, OC / 32, 9), 256>>>(conv_w);
    xtrans_kernel<<<dim3(IC / 32, HH, BN), 256>>>(x);

    static bool attr_set = false;
    if (!attr_set) {
        cudaFuncSetAttribute(conv_mma_kernel,
                             cudaFuncAttributeMaxDynamicSharedMemorySize, SM_HALVES * 2);
        attr_set = true;
    }
    conv_mma_kernel<<<dim3(8, 4, BN), 256, SM_HALVES * 2>>>(y);
}